// round 9
// baseline (speedup 1.0000x reference)
#include <cuda_runtime.h>
#include <cstdint>

// GraphAttention collapsed form (validated R1-R8, rel_err ~2e-7):
//   v[b,n] = x[b, NEF + n];  c1 = W.a[:64], c2 = W.a[64:]  (exp2-scaled)
//   w(i,o) = exp2(lrelu(c1*v[i] + c2*v[(i+o)%N])), o in [0,17)
//   denom[b] = sum w;  s[i] = sum_o w*v[(i+o)%N]
//   out[b,i,f] = lrelu(W[f]*s[i]) / denom[b]
//
// R9 = R8 with the exchange latency hidden: the edge loop computes esum only
// (weights cached in registers); the CTA partial is reduced and PUSHED to all
// peers, and the numerator s-loop + ssn write + pre-store sync execute while
// the 8 remote mbarrier arrives are in flight. The wait then takes the
// already-complete fast path instead of an exposed ~300-cycle wakeup.

#define NB      8
#define NN      4096
#define NOFF    17
#define FOUT    64
#define NEF     4096
#define CPB     8
#define TPB     512
#define BNODES  512
#define GRID    (NB * CPB)
#define LOG2E   1.4426950408889634f

__device__ __forceinline__ float lrelu(float z) { return fmaxf(z, 0.01f * z); }

__device__ __forceinline__ float warp_sum(float p) {
#pragma unroll
    for (int off = 16; off > 0; off >>= 1)
        p += __shfl_down_sync(0xffffffffu, p, off);
    return p;
}

__device__ __forceinline__ uint32_t smem_u32(const void* p) {
    uint32_t r;
    asm("{ .reg .u64 t; cvta.to.shared.u64 t, %1; cvt.u32.u64 %0, t; }"
        : "=r"(r) : "l"(p));
    return r;
}

__global__ void __launch_bounds__(TPB, 1) __cluster_dims__(CPB, 1, 1)
ga_fused(const float* __restrict__ x,
         const float* __restrict__ W,
         const float* __restrict__ a,
         float* __restrict__ out) {
    __shared__ float sv[BNODES + 16];
    __shared__ float ssn[BNODES];
    __shared__ float sW[FOUT];
    __shared__ float sred[16];
    __shared__ float sc[2];
    __shared__ float slots[CPB];           // inbound partials, one per rank
    __shared__ __align__(8) uint64_t mbar;

    const int b    = blockIdx.x >> 3;
    const int rank = blockIdx.x & (CPB - 1);
    const int base = rank * BNODES;
    const float* v = x + (size_t)b * (NEF + NN) + NEF;
    const int t    = threadIdx.x;
    const int warp = t >> 5;
    const int lane = t & 31;

    const uint32_t mbar_a = smem_u32(&mbar);
    if (t == 0)
        asm volatile("mbarrier.init.shared.b64 [%0], %1;"
                     :: "r"(mbar_a), "r"((uint32_t)CPB) : "memory");

    // Parallel prologue (disjoint warp roles):
    sv[t] = v[(base + t) & (NN - 1)];
    if (t < 16) sv[BNODES + t] = v[(base + BNODES + t) & (NN - 1)];
    if (warp == 14) {            // c1 = (W . a[:64]) * log2e
        float p = fmaf(W[lane], a[lane], W[lane + 32] * a[lane + 32]);
        p = warp_sum(p);
        if (lane == 0) sc[0] = p * LOG2E;
    } else if (warp == 15) {     // c2 = (W . a[64:]) * log2e
        float p = fmaf(W[lane], a[64 + lane], W[lane + 32] * a[96 + lane]);
        p = warp_sum(p);
        if (lane == 0) sc[1] = p * LOG2E;
    } else if (warp == 13) {
        sW[lane]      = W[lane];
        sW[lane + 32] = W[lane + 32];
    }
    __syncthreads();             // sv/sc/sW/mbar-init complete

    // Release mbar init to the cluster; matching wait after the reduce.
    asm volatile("barrier.cluster.arrive.aligned;" ::: "memory");

    // Store-phase weights hoisted (constant per thread).
    const float4 wvec = ((const float4*)sW)[t & 15];

    // Phase 1a: edge weights (cached) + thread-local exp-sum.
    const float c1 = sc[0], c2 = sc[1];
    const float vi = sv[t];
    const float c1vi = c1 * vi;
    float wreg[NOFF];
    float esum = 0.0f;
#pragma unroll
    for (int o = 0; o < NOFF; o++) {
        const float vj = sv[t + o];
        wreg[o] = exp2f(lrelu(fmaf(c2, vj, c1vi)));
        esum += wreg[o];
    }

    const float ws = warp_sum(esum);
    if (lane == 0) sred[warp] = ws;
    __syncthreads();             // sred complete

    // Init-visibility barrier: nearly free by now.
    asm volatile("barrier.cluster.wait.aligned;" ::: "memory");

    // Warp 0: combine 16 warp-partials, lanes 0-7 push to every peer's
    // slots[rank] + remote arrive (release). Fire-and-forget.
    if (warp == 0) {
        float p = (lane < 16) ? sred[lane] : 0.0f;
#pragma unroll
        for (int off = 8; off > 0; off >>= 1)
            p += __shfl_xor_sync(0xffffffffu, p, off);
        if (lane < CPB) {
            const uint32_t laddr = smem_u32(&slots[rank]);
            uint32_t rs, rm;
            asm("mapa.shared::cluster.u32 %0, %1, %2;"
                : "=r"(rs) : "r"(laddr), "r"((uint32_t)lane));
            asm volatile("st.shared::cluster.f32 [%0], %1;"
                         :: "r"(rs), "f"(p) : "memory");
            asm("mapa.shared::cluster.u32 %0, %1, %2;"
                : "=r"(rm) : "r"(mbar_a), "r"((uint32_t)lane));
            asm volatile("mbarrier.arrive.release.cluster.shared::cluster.b64 _, [%0];"
                         :: "r"(rm) : "memory");
        }
    }

    // Phase 1b: numerator from cached weights — executes while the remote
    // arrives are in flight (hides the exchange latency).
    float s = 0.0f;
#pragma unroll
    for (int o = 0; o < NOFF; o++)
        s = fmaf(wreg[o], sv[t + o], s);
    ssn[t] = s;
    __syncthreads();             // ssn visible to all warps (store reads cross-thread)

    // Wait for the 8 inbound partials (parity 0: re-inited every launch ->
    // graph-replay safe). Should hit the already-complete fast path.
    {
        uint32_t done;
        asm volatile(
            "{\n\t.reg .pred p;\n\t"
            "mbarrier.try_wait.parity.acquire.cluster.shared::cta.b64 p, [%1], %2;\n\t"
            "selp.b32 %0, 1, 0, p;\n\t}"
            : "=r"(done) : "r"(mbar_a), "r"(0u) : "memory");
        if (!done) {
            asm volatile(
                "{\n\t.reg .pred P1;\n\t"
                "WAIT_LOOP_%=:\n\t"
                "mbarrier.try_wait.parity.acquire.cluster.shared::cta.b64 P1, [%0], %1, 0x989680;\n\t"
                "@P1 bra.uni WAIT_DONE_%=;\n\t"
                "bra.uni WAIT_LOOP_%=;\n\t"
                "WAIT_DONE_%=:\n\t}"
                :: "r"(mbar_a), "r"(0u) : "memory");
        }
    }

    // Every warp sums the 8 slots itself (fixed shuffle order, deterministic),
    // then folds 1/denom into the weight vector ONCE.
    float p = slots[lane & 7];
#pragma unroll
    for (int off = 4; off > 0; off >>= 1)
        p += __shfl_xor_sync(0xffffffffu, p, off);
    const float inv = 1.0f / p;
    const float4 wv = make_float4(wvec.x * inv, wvec.y * inv,
                                  wvec.z * inv, wvec.w * inv);

    // Phase 2: 512 nodes x 64 feats = 8192 float4, fully coalesced.
    float4* o4 = (float4*)(out + ((size_t)b * NN + base) * FOUT);
    const int nbase = t >> 4;
#pragma unroll
    for (int k = 0; k < 16; k++) {
        const float sn = ssn[nbase + k * 32];
        float4 r;
        r.x = lrelu(sn * wv.x);
        r.y = lrelu(sn * wv.y);
        r.z = lrelu(sn * wv.z);
        r.w = lrelu(sn * wv.w);
        o4[t + k * TPB] = r;
    }
}

extern "C" void kernel_launch(void* const* d_in, const int* in_sizes, int n_in,
                              void* d_out, int out_size) {
    const float* x = (const float*)d_in[0];
    const float* W = (const float*)d_in[1];
    const float* a = (const float*)d_in[2];
    float* out = (float*)d_out;

    ga_fused<<<GRID, TPB>>>(x, W, a, out);
}

// round 10
// speedup vs baseline: 1.1383x; 1.1383x over previous
#include <cuda_runtime.h>
#include <cstdint>

// GraphAttention collapsed form (validated R1-R9, rel_err ~2e-7):
//   v[b,n] = x[b, NEF + n];  c1 = W.a[:64], c2 = W.a[64:]  (exp2-scaled)
//   w(i,o) = exp2(lrelu(c1*v[i] + c2*v[(i+o)%N])), o in [0,17)
//   denom[b] = sum w;  s[i] = sum_o w*v[(i+o)%N]
//   out[b,i,f] = lrelu(W[f]*s[i]) / denom[b]
//
// R10 = R8 (best-bench skeleton, fused esum+s edge loop) with the numerator
// broadcast converted from block-level (ssn smem + __syncthreads) to
// WARP-level: node 32w+2j+(lane>>4) belongs to a lane of the same warp, so
// the store loop fetches s via __shfl_sync. Removes the ssn array, one
// STS/LDS round trip, and the final block barrier -- warps flow from the
// mbarrier wait straight into their coalesced 512-float4 store region.

#define NB      8
#define NN      4096
#define NOFF    17
#define FOUT    64
#define NEF     4096
#define CPB     8
#define TPB     512
#define BNODES  512
#define GRID    (NB * CPB)
#define LOG2E   1.4426950408889634f

__device__ __forceinline__ float lrelu(float z) { return fmaxf(z, 0.01f * z); }

__device__ __forceinline__ float warp_sum(float p) {
#pragma unroll
    for (int off = 16; off > 0; off >>= 1)
        p += __shfl_down_sync(0xffffffffu, p, off);
    return p;
}

__device__ __forceinline__ uint32_t smem_u32(const void* p) {
    uint32_t r;
    asm("{ .reg .u64 t; cvta.to.shared.u64 t, %1; cvt.u32.u64 %0, t; }"
        : "=r"(r) : "l"(p));
    return r;
}

__global__ void __launch_bounds__(TPB, 1) __cluster_dims__(CPB, 1, 1)
ga_fused(const float* __restrict__ x,
         const float* __restrict__ W,
         const float* __restrict__ a,
         float* __restrict__ out) {
    __shared__ float sv[BNODES + 16];
    __shared__ float sW[FOUT];
    __shared__ float sred[16];
    __shared__ float sc[2];
    __shared__ float slots[CPB];           // inbound partials, one per rank
    __shared__ __align__(8) uint64_t mbar;

    const int b    = blockIdx.x >> 3;
    const int rank = blockIdx.x & (CPB - 1);
    const int base = rank * BNODES;
    const float* v = x + (size_t)b * (NEF + NN) + NEF;
    const int t    = threadIdx.x;
    const int warp = t >> 5;
    const int lane = t & 31;

    const uint32_t mbar_a = smem_u32(&mbar);
    if (t == 0)
        asm volatile("mbarrier.init.shared.b64 [%0], %1;"
                     :: "r"(mbar_a), "r"((uint32_t)CPB) : "memory");

    // Parallel prologue (disjoint warp roles):
    sv[t] = v[(base + t) & (NN - 1)];
    if (t < 16) sv[BNODES + t] = v[(base + BNODES + t) & (NN - 1)];
    if (warp == 14) {            // c1 = (W . a[:64]) * log2e
        float p = fmaf(W[lane], a[lane], W[lane + 32] * a[lane + 32]);
        p = warp_sum(p);
        if (lane == 0) sc[0] = p * LOG2E;
    } else if (warp == 15) {     // c2 = (W . a[64:]) * log2e
        float p = fmaf(W[lane], a[64 + lane], W[lane + 32] * a[96 + lane]);
        p = warp_sum(p);
        if (lane == 0) sc[1] = p * LOG2E;
    } else if (warp == 13) {
        sW[lane]      = W[lane];
        sW[lane + 32] = W[lane + 32];
    }
    __syncthreads();             // sv/sc/sW/mbar-init complete

    // Release mbar init to the cluster; matching wait after the reduce.
    asm volatile("barrier.cluster.arrive.aligned;" ::: "memory");

    // Store-phase weights (constant per lane: float4 index within node
    // is lane&15 for every store iteration).
    const float4 wvec = ((const float4*)sW)[lane & 15];

    // Phase 1: fused edge loop -- per-node numerator s + exp-sum.
    const float c1 = sc[0], c2 = sc[1];
    const float vi = sv[t];
    const float c1vi = c1 * vi;
    float esum = 0.0f, s = 0.0f;
#pragma unroll
    for (int o = 0; o < NOFF; o++) {
        const float vj = sv[t + o];
        const float w  = exp2f(lrelu(fmaf(c2, vj, c1vi)));
        esum += w;
        s = fmaf(w, vj, s);
    }

    const float ws = warp_sum(esum);
    if (lane == 0) sred[warp] = ws;
    __syncthreads();             // sred complete

    // Init-visibility barrier: hidden under the compute above.
    asm volatile("barrier.cluster.wait.aligned;" ::: "memory");

    // Warp 0: combine 16 warp-partials, lanes 0-7 push to every peer's
    // slots[rank] + remote arrive (release).
    if (warp == 0) {
        float p = (lane < 16) ? sred[lane] : 0.0f;
#pragma unroll
        for (int off = 8; off > 0; off >>= 1)
            p += __shfl_xor_sync(0xffffffffu, p, off);
        if (lane < CPB) {
            const uint32_t laddr = smem_u32(&slots[rank]);
            uint32_t rs, rm;
            asm("mapa.shared::cluster.u32 %0, %1, %2;"
                : "=r"(rs) : "r"(laddr), "r"((uint32_t)lane));
            asm volatile("st.shared::cluster.f32 [%0], %1;"
                         :: "r"(rs), "f"(p) : "memory");
            asm("mapa.shared::cluster.u32 %0, %1, %2;"
                : "=r"(rm) : "r"(mbar_a), "r"((uint32_t)lane));
            asm volatile("mbarrier.arrive.release.cluster.shared::cluster.b64 _, [%0];"
                         :: "r"(rm) : "memory");
        }
    }

    // All threads wait for the 8 inbound partials (parity 0: mbar re-inited
    // every launch -> graph-replay safe). Acquire publishes the remote stores.
    {
        uint32_t done;
        asm volatile(
            "{\n\t.reg .pred p;\n\t"
            "mbarrier.try_wait.parity.acquire.cluster.shared::cta.b64 p, [%1], %2;\n\t"
            "selp.b32 %0, 1, 0, p;\n\t}"
            : "=r"(done) : "r"(mbar_a), "r"(0u) : "memory");
        if (!done) {
            asm volatile(
                "{\n\t.reg .pred P1;\n\t"
                "WAIT_LOOP_%=:\n\t"
                "mbarrier.try_wait.parity.acquire.cluster.shared::cta.b64 P1, [%0], %1, 0x989680;\n\t"
                "@P1 bra.uni WAIT_DONE_%=;\n\t"
                "bra.uni WAIT_LOOP_%=;\n\t"
                "WAIT_DONE_%=:\n\t}"
                :: "r"(mbar_a), "r"(0u) : "memory");
        }
    }

    // Per-warp slot sum (fixed shuffle order -> deterministic); fold 1/denom
    // into the weight vector once.
    float p = slots[lane & 7];
#pragma unroll
    for (int off = 4; off > 0; off >>= 1)
        p += __shfl_xor_sync(0xffffffffu, p, off);
    const float inv = 1.0f / p;
    const float4 wv = make_float4(wvec.x * inv, wvec.y * inv,
                                  wvec.z * inv, wvec.w * inv);

    // Phase 2: warp-local stores, no block sync, no ssn smem.
    // Warp w owns nodes [32w, 32w+32): 32 nodes x 16 float4 = 512 float4,
    // region out4 + (base + 32w)*16, index lane + 32j (coalesced per j).
    // Numerator for iteration j on lane l lives in lane 2j + (l>>4).
    float4* o4w = (float4*)(out + ((size_t)b * NN + base + warp * 32) * FOUT);
    const int hi = lane >> 4;
#pragma unroll
    for (int j = 0; j < 16; j++) {
        const float sn = __shfl_sync(0xffffffffu, s, 2 * j + hi);
        float4 r;
        r.x = lrelu(sn * wv.x);
        r.y = lrelu(sn * wv.y);
        r.z = lrelu(sn * wv.z);
        r.w = lrelu(sn * wv.w);
        o4w[lane + 32 * j] = r;
    }
}

extern "C" void kernel_launch(void* const* d_in, const int* in_sizes, int n_in,
                              void* d_out, int out_size) {
    const float* x = (const float*)d_in[0];
    const float* W = (const float*)d_in[1];
    const float* a = (const float*)d_in[2];
    float* out = (float*)d_out;

    ga_fused<<<GRID, TPB>>>(x, W, a, out);
}